// round 3
// baseline (speedup 1.0000x reference)
#include <cuda_runtime.h>
#include <math.h>

#define SEQ 4096
#define DMODEL 1024

// Scratch (allocation-free rule: __device__ globals)
__device__ float g_Q[(size_t)SEQ * DMODEL];
__device__ float g_K[(size_t)SEQ * DMODEL];
__device__ float g_V[(size_t)SEQ * DMODEL];
__device__ float g_S[(size_t)SEQ * SEQ];

// ---------------------------------------------------------------------------
// SGEMM: C = alpha * A @ B   (BT=false: B is [K,N] row-major)
//        C = alpha * A @ B^T (BT=true : B is [N,K] row-major)
// Tiles: BM=BN=128, BK=16. 256 threads, 8x8 microtile per thread.
// All of M,N,K assumed multiples of tile dims (true for this problem).
// ---------------------------------------------------------------------------
template <bool BT>
__global__ __launch_bounds__(256, 2)
void sgemm_kernel(const float* __restrict__ A,
                  const float* __restrict__ B,
                  float* __restrict__ C,
                  int M, int N, int Kdim, float alpha)
{
    constexpr int BM = 128, BN = 128, BK = 16;
    __shared__ float As[BK][BM + 4];   // +4 pad: bank-conflict relief, keeps 16B align
    __shared__ float Bs[BK][BN + 4];

    const int tid = threadIdx.x;
    const int bx = blockIdx.x;   // N-tile
    const int by = blockIdx.y;   // M-tile

    const float* Ablk = A + (size_t)by * BM * Kdim;
    float* Cblk = C + (size_t)by * BM * N + (size_t)bx * BN;

    const int tx = tid & 15;     // 0..15 -> column group
    const int ty = tid >> 4;     // 0..15 -> row group

    float acc[8][8];
    #pragma unroll
    for (int i = 0; i < 8; i++)
        #pragma unroll
        for (int j = 0; j < 8; j++) acc[i][j] = 0.f;

    for (int k0 = 0; k0 < Kdim; k0 += BK) {
        // --- load A tile (BM x BK), store transposed: As[k][m] ---
        // 128*16 floats = 512 float4; 256 threads * 2
        #pragma unroll
        for (int l = 0; l < 2; l++) {
            int i = tid + l * 256;          // float4 index
            int row  = i >> 2;              // 0..127
            int col4 = (i & 3) << 2;        // 0,4,8,12
            float4 v = *(const float4*)(Ablk + (size_t)row * Kdim + k0 + col4);
            As[col4 + 0][row] = v.x;
            As[col4 + 1][row] = v.y;
            As[col4 + 2][row] = v.z;
            As[col4 + 3][row] = v.w;
        }
        // --- load B tile into Bs[k][n] ---
        if (!BT) {
            // B[K,N] row-major: contiguous along n
            #pragma unroll
            for (int l = 0; l < 2; l++) {
                int i = tid + l * 256;
                int row  = i >> 5;          // 0..15 (k within tile)
                int col4 = (i & 31) << 2;   // 0..124
                *(float4*)&Bs[row][col4] =
                    *(const float4*)(B + (size_t)(k0 + row) * N + (size_t)bx * BN + col4);
            }
        } else {
            // B[N,K] row-major: contiguous along k, scatter-transpose into Bs
            #pragma unroll
            for (int l = 0; l < 2; l++) {
                int i = tid + l * 256;
                int n  = i >> 2;            // 0..127
                int k4 = (i & 3) << 2;      // 0,4,8,12
                float4 v = *(const float4*)(B + (size_t)(bx * BN + n) * Kdim + k0 + k4);
                Bs[k4 + 0][n] = v.x;
                Bs[k4 + 1][n] = v.y;
                Bs[k4 + 2][n] = v.z;
                Bs[k4 + 3][n] = v.w;
            }
        }
        __syncthreads();

        #pragma unroll
        for (int k = 0; k < BK; k++) {
            float4 a0 = *(const float4*)&As[k][ty * 8];
            float4 a1 = *(const float4*)&As[k][ty * 8 + 4];
            float4 b0 = *(const float4*)&Bs[k][tx * 8];
            float4 b1 = *(const float4*)&Bs[k][tx * 8 + 4];
            float a[8] = {a0.x, a0.y, a0.z, a0.w, a1.x, a1.y, a1.z, a1.w};
            float b[8] = {b0.x, b0.y, b0.z, b0.w, b1.x, b1.y, b1.z, b1.w};
            #pragma unroll
            for (int i = 0; i < 8; i++)
                #pragma unroll
                for (int j = 0; j < 8; j++)
                    acc[i][j] = fmaf(a[i], b[j], acc[i][j]);
        }
        __syncthreads();
    }

    #pragma unroll
    for (int i = 0; i < 8; i++) {
        float* crow = Cblk + (size_t)(ty * 8 + i) * N + tx * 8;
        #pragma unroll
        for (int j = 0; j < 8; j += 4) {
            float4 v = make_float4(acc[i][j] * alpha, acc[i][j + 1] * alpha,
                                   acc[i][j + 2] * alpha, acc[i][j + 3] * alpha);
            *(float4*)(crow + j) = v;
        }
    }
}

// ---------------------------------------------------------------------------
// Row softmax over S[SEQ][SEQ], in place. One block per row, 256 threads.
// ---------------------------------------------------------------------------
__global__ __launch_bounds__(256)
void softmax_kernel(float* __restrict__ S)
{
    constexpr int T = 256;
    constexpr int NV = SEQ / 4 / T;     // 4 float4 per thread
    __shared__ float red[8];
    __shared__ float bcast;

    const int tid = threadIdx.x;
    float4* p = (float4*)(S + (size_t)blockIdx.x * SEQ);

    float4 v[NV];
    float mx = -INFINITY;
    #pragma unroll
    for (int i = 0; i < NV; i++) {
        v[i] = p[tid + i * T];
        mx = fmaxf(mx, fmaxf(fmaxf(v[i].x, v[i].y), fmaxf(v[i].z, v[i].w)));
    }
    #pragma unroll
    for (int o = 16; o; o >>= 1) mx = fmaxf(mx, __shfl_xor_sync(0xffffffffu, mx, o));
    if ((tid & 31) == 0) red[tid >> 5] = mx;
    __syncthreads();
    if (tid == 0) {
        float m = red[0];
        #pragma unroll
        for (int i = 1; i < 8; i++) m = fmaxf(m, red[i]);
        bcast = m;
    }
    __syncthreads();
    mx = bcast;

    float sum = 0.f;
    #pragma unroll
    for (int i = 0; i < NV; i++) {
        v[i].x = __expf(v[i].x - mx);
        v[i].y = __expf(v[i].y - mx);
        v[i].z = __expf(v[i].z - mx);
        v[i].w = __expf(v[i].w - mx);
        sum += (v[i].x + v[i].y) + (v[i].z + v[i].w);
    }
    #pragma unroll
    for (int o = 16; o; o >>= 1) sum += __shfl_xor_sync(0xffffffffu, sum, o);
    __syncthreads();                     // protect red[] (tid0 read above done)
    if ((tid & 31) == 0) red[tid >> 5] = sum;
    __syncthreads();
    if (tid == 0) {
        float s = 0.f;
        #pragma unroll
        for (int i = 0; i < 8; i++) s += red[i];
        bcast = 1.f / s;
    }
    __syncthreads();
    const float inv = bcast;

    #pragma unroll
    for (int i = 0; i < NV; i++) {
        v[i].x *= inv; v[i].y *= inv; v[i].z *= inv; v[i].w *= inv;
        p[tid + i * T] = v[i];
    }
}

// ---------------------------------------------------------------------------
extern "C" void kernel_launch(void* const* d_in, const int* in_sizes, int n_in,
                              void* d_out, int out_size)
{
    const float* E  = (const float*)d_in[0];   // [SEQ, DMODEL]
    const float* Wq = (const float*)d_in[1];   // [DMODEL, DMODEL]
    const float* Wk = (const float*)d_in[2];
    const float* Wv = (const float*)d_in[3];
    float* out = (float*)d_out;                // [SEQ, DMODEL]

    float *Q, *K, *V, *S;
    cudaGetSymbolAddress((void**)&Q, g_Q);
    cudaGetSymbolAddress((void**)&K, g_K);
    cudaGetSymbolAddress((void**)&V, g_V);
    cudaGetSymbolAddress((void**)&S, g_S);

    dim3 blk(256);
    // QKV projections: [4096,1024] = [4096,1024] @ [1024,1024]
    dim3 gqkv(DMODEL / 128, SEQ / 128);
    sgemm_kernel<false><<<gqkv, blk>>>(E, Wq, Q, SEQ, DMODEL, DMODEL, 1.0f);
    sgemm_kernel<false><<<gqkv, blk>>>(E, Wk, K, SEQ, DMODEL, DMODEL, 1.0f);
    sgemm_kernel<false><<<gqkv, blk>>>(E, Wv, V, SEQ, DMODEL, DMODEL, 1.0f);

    // Scores: S = (Q @ K^T) / sqrt(1024)
    dim3 gs(SEQ / 128, SEQ / 128);
    sgemm_kernel<true><<<gs, blk>>>(Q, K, S, SEQ, SEQ, DMODEL, 0.03125f);

    // Row softmax in place
    softmax_kernel<<<SEQ, blk>>>(S);

    // Output: out = P @ V
    dim3 go(DMODEL / 128, SEQ / 128);
    sgemm_kernel<false><<<go, blk>>>(S, V, out, SEQ, DMODEL, SEQ, 1.0f);
}

// round 5
// speedup vs baseline: 2.9462x; 2.9462x over previous
#include <cuda_runtime.h>
#include <math.h>
#include <stdint.h>

#define SEQ 4096
#define DMODEL 1024

// Scratch (allocation-free rule: __device__ globals)
__device__ float g_Q[(size_t)SEQ * DMODEL];
__device__ float g_K[(size_t)SEQ * DMODEL];
__device__ float g_V[(size_t)SEQ * DMODEL];
__device__ float g_S[(size_t)SEQ * SEQ];

// ---------------------------------------------------------------------------
// helpers
// ---------------------------------------------------------------------------
__device__ __forceinline__ uint32_t f2tf(float x) {
    uint32_t r;
    asm("cvt.rna.tf32.f32 %0, %1;" : "=r"(r) : "f"(x));
    return r;
}

__device__ __forceinline__ void cpa16(float* s, const float* g) {
    uint32_t sa = (uint32_t)__cvta_generic_to_shared(s);
    asm volatile("cp.async.cg.shared.global [%0], [%1], 16;" :: "r"(sa), "l"(g));
}
__device__ __forceinline__ void cpa_commit() {
    asm volatile("cp.async.commit_group;");
}
template <int N>
__device__ __forceinline__ void cpa_wait() {
    asm volatile("cp.async.wait_group %0;" :: "n"(N));
}

__device__ __forceinline__ void mma_tf32(float c[4], const uint32_t a[4], const uint32_t b[2]) {
    asm volatile(
        "mma.sync.aligned.m16n8k8.row.col.f32.tf32.tf32.f32 "
        "{%0,%1,%2,%3}, {%4,%5,%6,%7}, {%8,%9}, {%0,%1,%2,%3};"
        : "+f"(c[0]), "+f"(c[1]), "+f"(c[2]), "+f"(c[3])
        : "r"(a[0]), "r"(a[1]), "r"(a[2]), "r"(a[3]), "r"(b[0]), "r"(b[1]));
}

// ---------------------------------------------------------------------------
// TF32 tensor-core GEMM: C = alpha * A @ B   (BT=false: B is [K,N] row-major)
//                        C = alpha * A @ B^T (BT=true : B is [N,K] row-major)
// CTA tile 128x128x32, 256 threads (8 warps), warp tile 64x32.
// Smem layouts (all conflict-free for m16n8k8 fragment reads):
//   As: [128][36]  ([m][k], pad 4) -> direct 16B copies from row-major A
//   Bs NN: [32][136] ([k][n], pad 8) -> direct copies from row-major B
//   Bs NT: [128][36] ([n][k], pad 4) -> direct copies from row-major B
// cp.async double-buffered. All dims multiples of tile dims (no predication).
// ---------------------------------------------------------------------------
template <bool BT>
__global__ __launch_bounds__(256, 2)
void tf32_gemm(const float* __restrict__ A,
               const float* __restrict__ B,
               float* __restrict__ C,
               int M, int N, int K, float alpha)
{
    constexpr int AS    = 128 * 36;                    // floats
    constexpr int BSZ   = BT ? 128 * 36 : 32 * 136;    // floats
    constexpr int BUF   = AS + BSZ;

    extern __shared__ float sm[];

    const int tid  = threadIdx.x;
    const int lane = tid & 31;
    const int wid  = tid >> 5;
    const int warp_m = (wid & 1) * 64;   // 2 warps in M
    const int warp_n = (wid >> 1) * 32;  // 4 warps in N
    const int bx = blockIdx.x;           // N-tile
    const int by = blockIdx.y;           // M-tile

    const int NT = K / 32;

    // ---- tile prefetch ----
    auto load_tile = [&](int buf, int k0) {
        float* As = sm + buf * BUF;
        float* Bs = As + AS;
        #pragma unroll
        for (int l = 0; l < 4; l++) {
            int c = tid + l * 256;
            int row = c >> 3, cj = (c & 7) << 2;
            cpa16(As + row * 36 + cj,
                  A + (size_t)(by * 128 + row) * K + k0 + cj);
        }
        if (!BT) {
            #pragma unroll
            for (int l = 0; l < 4; l++) {
                int c = tid + l * 256;
                int row = c >> 5, cj = (c & 31) << 2;
                cpa16(Bs + row * 136 + cj,
                      B + (size_t)(k0 + row) * N + bx * 128 + cj);
            }
        } else {
            #pragma unroll
            for (int l = 0; l < 4; l++) {
                int c = tid + l * 256;
                int row = c >> 3, cj = (c & 7) << 2;
                cpa16(Bs + row * 36 + cj,
                      B + (size_t)(bx * 128 + row) * K + k0 + cj);
            }
        }
        cpa_commit();
    };

    float acc[4][4][4];
    #pragma unroll
    for (int i = 0; i < 4; i++)
        #pragma unroll
        for (int j = 0; j < 4; j++)
            #pragma unroll
            for (int r = 0; r < 4; r++) acc[i][j][r] = 0.f;

    load_tile(0, 0);

    int cur = 0;
    for (int kt = 0; kt < NT; kt++) {
        if (kt + 1 < NT) {
            load_tile(cur ^ 1, (kt + 1) * 32);
            cpa_wait<1>();
        } else {
            cpa_wait<0>();
        }
        __syncthreads();

        const float* As = sm + cur * BUF;
        const float* Bs = As + AS;

        #pragma unroll
        for (int ks = 0; ks < 4; ks++) {
            const int kk = ks * 8;
            uint32_t a[4][4];
            uint32_t b[4][2];

            const int arow = warp_m + (lane >> 2);
            const int acol = kk + (lane & 3);
            #pragma unroll
            for (int mf = 0; mf < 4; mf++) {
                const float* p = As + (size_t)(arow + mf * 16) * 36 + acol;
                a[mf][0] = f2tf(p[0]);
                a[mf][1] = f2tf(p[8 * 36]);
                a[mf][2] = f2tf(p[4]);
                a[mf][3] = f2tf(p[8 * 36 + 4]);
            }
            if (!BT) {
                const float* pb = Bs + (size_t)(kk + (lane & 3)) * 136
                                     + warp_n + (lane >> 2);
                #pragma unroll
                for (int nf = 0; nf < 4; nf++) {
                    b[nf][0] = f2tf(pb[nf * 8]);
                    b[nf][1] = f2tf(pb[nf * 8 + 4 * 136]);
                }
            } else {
                #pragma unroll
                for (int nf = 0; nf < 4; nf++) {
                    const float* pb = Bs + (size_t)(warp_n + nf * 8 + (lane >> 2)) * 36
                                         + kk + (lane & 3);
                    b[nf][0] = f2tf(pb[0]);
                    b[nf][1] = f2tf(pb[4]);
                }
            }
            #pragma unroll
            for (int mf = 0; mf < 4; mf++)
                #pragma unroll
                for (int nf = 0; nf < 4; nf++)
                    mma_tf32(acc[mf][nf], a[mf], b[nf]);
        }
        __syncthreads();
        cur ^= 1;
    }

    // ---- epilogue ----
    const int crow = by * 128 + warp_m + (lane >> 2);
    const int ccol = bx * 128 + warp_n + ((lane & 3) << 1);
    #pragma unroll
    for (int mf = 0; mf < 4; mf++) {
        #pragma unroll
        for (int nf = 0; nf < 4; nf++) {
            float2 v0 = make_float2(acc[mf][nf][0] * alpha, acc[mf][nf][1] * alpha);
            float2 v1 = make_float2(acc[mf][nf][2] * alpha, acc[mf][nf][3] * alpha);
            *(float2*)(C + (size_t)(crow + mf * 16) * N + ccol + nf * 8)     = v0;
            *(float2*)(C + (size_t)(crow + mf * 16 + 8) * N + ccol + nf * 8) = v1;
        }
    }
}

// ---------------------------------------------------------------------------
// Row softmax over S[SEQ][SEQ], in place. One block per row, 256 threads.
// ---------------------------------------------------------------------------
__global__ __launch_bounds__(256)
void softmax_kernel(float* __restrict__ S)
{
    constexpr int T = 256;
    constexpr int NV = SEQ / 4 / T;
    __shared__ float red[8];
    __shared__ float bcast;

    const int tid = threadIdx.x;
    float4* p = (float4*)(S + (size_t)blockIdx.x * SEQ);

    float4 v[NV];
    float mx = -INFINITY;
    #pragma unroll
    for (int i = 0; i < NV; i++) {
        v[i] = p[tid + i * T];
        mx = fmaxf(mx, fmaxf(fmaxf(v[i].x, v[i].y), fmaxf(v[i].z, v[i].w)));
    }
    #pragma unroll
    for (int o = 16; o; o >>= 1) mx = fmaxf(mx, __shfl_xor_sync(0xffffffffu, mx, o));
    if ((tid & 31) == 0) red[tid >> 5] = mx;
    __syncthreads();
    if (tid == 0) {
        float m = red[0];
        #pragma unroll
        for (int i = 1; i < 8; i++) m = fmaxf(m, red[i]);
        bcast = m;
    }
    __syncthreads();
    mx = bcast;

    float sum = 0.f;
    #pragma unroll
    for (int i = 0; i < NV; i++) {
        v[i].x = __expf(v[i].x - mx);
        v[i].y = __expf(v[i].y - mx);
        v[i].z = __expf(v[i].z - mx);
        v[i].w = __expf(v[i].w - mx);
        sum += (v[i].x + v[i].y) + (v[i].z + v[i].w);
    }
    #pragma unroll
    for (int o = 16; o; o >>= 1) sum += __shfl_xor_sync(0xffffffffu, sum, o);
    __syncthreads();
    if ((tid & 31) == 0) red[tid >> 5] = sum;
    __syncthreads();
    if (tid == 0) {
        float s = 0.f;
        #pragma unroll
        for (int i = 0; i < 8; i++) s += red[i];
        bcast = 1.f / s;
    }
    __syncthreads();
    const float inv = bcast;

    #pragma unroll
    for (int i = 0; i < NV; i++) {
        v[i].x *= inv; v[i].y *= inv; v[i].z *= inv; v[i].w *= inv;
        p[tid + i * T] = v[i];
    }
}

// ---------------------------------------------------------------------------
extern "C" void kernel_launch(void* const* d_in, const int* in_sizes, int n_in,
                              void* d_out, int out_size)
{
    const float* E  = (const float*)d_in[0];   // [SEQ, DMODEL]
    const float* Wq = (const float*)d_in[1];   // [DMODEL, DMODEL]
    const float* Wk = (const float*)d_in[2];
    const float* Wv = (const float*)d_in[3];
    float* out = (float*)d_out;                // [SEQ, DMODEL]

    float *Q, *K, *V, *S;
    cudaGetSymbolAddress((void**)&Q, g_Q);
    cudaGetSymbolAddress((void**)&K, g_K);
    cudaGetSymbolAddress((void**)&V, g_V);
    cudaGetSymbolAddress((void**)&S, g_S);

    // dynamic smem sizes (bytes): NN = (128*36 + 32*136)*4, NT = (128*36*2)*4
    constexpr int SMEM_NN = 2 * (128 * 36 + 32 * 136) * 4;   // 71680
    constexpr int SMEM_NT = 2 * (128 * 36 + 128 * 36) * 4;   // 73728
    cudaFuncSetAttribute(tf32_gemm<false>,
                         cudaFuncAttributeMaxDynamicSharedMemorySize, SMEM_NN);
    cudaFuncSetAttribute(tf32_gemm<true>,
                         cudaFuncAttributeMaxDynamicSharedMemorySize, SMEM_NT);

    dim3 blk(256);

    // QKV projections: [4096,1024] = [4096,1024] @ [1024,1024]
    dim3 gqkv(DMODEL / 128, SEQ / 128);
    tf32_gemm<false><<<gqkv, blk, SMEM_NN>>>(E, Wq, Q, SEQ, DMODEL, DMODEL, 1.0f);
    tf32_gemm<false><<<gqkv, blk, SMEM_NN>>>(E, Wk, K, SEQ, DMODEL, DMODEL, 1.0f);
    tf32_gemm<false><<<gqkv, blk, SMEM_NN>>>(E, Wv, V, SEQ, DMODEL, DMODEL, 1.0f);

    // Scores: S = (Q @ K^T) / sqrt(1024)
    dim3 gs(SEQ / 128, SEQ / 128);
    tf32_gemm<true><<<gs, blk, SMEM_NT>>>(Q, K, S, SEQ, SEQ, DMODEL, 0.03125f);

    // Row softmax in place
    softmax_kernel<<<SEQ, blk>>>(S);

    // Output: out = P @ V
    dim3 go(DMODEL / 128, SEQ / 128);
    tf32_gemm<false><<<go, blk, SMEM_NN>>>(S, V, out, SEQ, DMODEL, SEQ, 1.0f);
}

// round 6
// speedup vs baseline: 3.1567x; 1.0715x over previous
#include <cuda_runtime.h>
#include <math.h>
#include <stdint.h>

#define SEQ 4096
#define DMODEL 1024
#define DQKV 3072   // Q|K|V concatenated

// Scratch (allocation-free rule: __device__ globals)
__device__ float g_E[(size_t)SEQ * DMODEL];     // tf32-rounded embeddings
__device__ float g_W[(size_t)DMODEL * DQKV];    // tf32-rounded [Wq|Wk|Wv]
__device__ float g_QKV[(size_t)SEQ * DQKV];     // Q|K|V, tf32-rounded
__device__ float g_S[(size_t)SEQ * SEQ];        // scores / probabilities

// ---------------------------------------------------------------------------
// helpers
// ---------------------------------------------------------------------------
__device__ __forceinline__ float rtf(float x) {
    uint32_t r;
    asm("cvt.rna.tf32.f32 %0, %1;" : "=r"(r) : "f"(x));
    return __uint_as_float(r);
}

__device__ __forceinline__ void cpa16(float* s, const float* g) {
    uint32_t sa = (uint32_t)__cvta_generic_to_shared(s);
    asm volatile("cp.async.cg.shared.global [%0], [%1], 16;" :: "r"(sa), "l"(g));
}
__device__ __forceinline__ void cpa_commit() {
    asm volatile("cp.async.commit_group;");
}
template <int N>
__device__ __forceinline__ void cpa_wait() {
    asm volatile("cp.async.wait_group %0;" :: "n"(N));
}

__device__ __forceinline__ void mma_tf32(float c[4], const uint32_t a[4], const uint32_t b[2]) {
    asm volatile(
        "mma.sync.aligned.m16n8k8.row.col.f32.tf32.tf32.f32 "
        "{%0,%1,%2,%3}, {%4,%5,%6,%7}, {%8,%9}, {%0,%1,%2,%3};"
        : "+f"(c[0]), "+f"(c[1]), "+f"(c[2]), "+f"(c[3])
        : "r"(a[0]), "r"(a[1]), "r"(a[2]), "r"(a[3]), "r"(b[0]), "r"(b[1]));
}

// ---------------------------------------------------------------------------
// Prepass: tf32-round a contiguous array (float4 granularity)
// ---------------------------------------------------------------------------
__global__ void round_copy4(const float4* __restrict__ src, float4* __restrict__ dst, int n4)
{
    int i = blockIdx.x * blockDim.x + threadIdx.x;
    if (i < n4) {
        float4 v = src[i];
        v.x = rtf(v.x); v.y = rtf(v.y); v.z = rtf(v.z); v.w = rtf(v.w);
        dst[i] = v;
    }
}

// Prepass: tf32-round + concat one W [1024x1024] into g_W column band (ld 3072)
__global__ void round_concat_w(const float* __restrict__ src, float* __restrict__ dst)
{
    int i = blockIdx.x * blockDim.x + threadIdx.x;   // 0..262143 float4 idx
    int r  = i >> 8;
    int c4 = (i & 255) << 2;
    float4 v = *(const float4*)(src + (size_t)r * DMODEL + c4);
    v.x = rtf(v.x); v.y = rtf(v.y); v.z = rtf(v.z); v.w = rtf(v.w);
    *(float4*)(dst + (size_t)r * DQKV + c4) = v;
}

// ---------------------------------------------------------------------------
// TF32 tensor-core GEMM (operands pre-rounded to tf32; no cvt in mainloop).
//   BT=false: C = alpha * A @ B    (B is [K,N] row-major, ld=ldb)
//   BT=true : C = alpha * A @ B^T  (B is [N,K] row-major, ld=ldb)
// ROUND_OUT: tf32-round C on store (for outputs consumed as GEMM operands).
// CTA tile 128x128x32, 256 threads (8 warps), warp tile 64x32.
// Smem: As [128][36] ([m][k] pad4); Bs NN [32][136]; Bs NT [128][36].
// cp.async double-buffered; fragment registers double-buffered across k-steps.
// ---------------------------------------------------------------------------
template <bool BT, bool ROUND_OUT>
__global__ __launch_bounds__(256, 2)
void tf32_gemm(const float* __restrict__ A, int lda,
               const float* __restrict__ B, int ldb,
               float* __restrict__ C, int ldc,
               int K, float alpha)
{
    constexpr int AS  = 128 * 36;
    constexpr int BSZ = BT ? 128 * 36 : 32 * 136;
    constexpr int BUF = AS + BSZ;

    extern __shared__ float sm[];

    const int tid  = threadIdx.x;
    const int lane = tid & 31;
    const int wid  = tid >> 5;
    const int warp_m = (wid & 1) * 64;
    const int warp_n = (wid >> 1) * 32;
    const int bx = blockIdx.x;
    const int by = blockIdx.y;

    const int NT = K / 32;

    auto load_tile = [&](int buf, int k0) {
        float* As = sm + buf * BUF;
        float* Bs = As + AS;
        #pragma unroll
        for (int l = 0; l < 4; l++) {
            int c = tid + l * 256;
            int row = c >> 3, cj = (c & 7) << 2;
            cpa16(As + row * 36 + cj,
                  A + (size_t)(by * 128 + row) * lda + k0 + cj);
        }
        if (!BT) {
            #pragma unroll
            for (int l = 0; l < 4; l++) {
                int c = tid + l * 256;
                int row = c >> 5, cj = (c & 31) << 2;
                cpa16(Bs + row * 136 + cj,
                      B + (size_t)(k0 + row) * ldb + bx * 128 + cj);
            }
        } else {
            #pragma unroll
            for (int l = 0; l < 4; l++) {
                int c = tid + l * 256;
                int row = c >> 3, cj = (c & 7) << 2;
                cpa16(Bs + row * 36 + cj,
                      B + (size_t)(bx * 128 + row) * ldb + k0 + cj);
            }
        }
        cpa_commit();
    };

    // fragment loader (raw bits — operands already tf32-rounded)
    auto lfrag = [&](const float* As, const float* Bs, int ks,
                     uint32_t a[4][4], uint32_t b[4][2]) {
        const int kk = ks * 8;
        const float* pa = As + (size_t)(warp_m + (lane >> 2)) * 36 + kk + (lane & 3);
        #pragma unroll
        for (int mf = 0; mf < 4; mf++) {
            const float* p = pa + mf * 16 * 36;
            a[mf][0] = __float_as_uint(p[0]);
            a[mf][1] = __float_as_uint(p[8 * 36]);
            a[mf][2] = __float_as_uint(p[4]);
            a[mf][3] = __float_as_uint(p[8 * 36 + 4]);
        }
        if (!BT) {
            const float* pb = Bs + (size_t)(kk + (lane & 3)) * 136 + warp_n + (lane >> 2);
            #pragma unroll
            for (int nf = 0; nf < 4; nf++) {
                b[nf][0] = __float_as_uint(pb[nf * 8]);
                b[nf][1] = __float_as_uint(pb[nf * 8 + 4 * 136]);
            }
        } else {
            #pragma unroll
            for (int nf = 0; nf < 4; nf++) {
                const float* pb = Bs + (size_t)(warp_n + nf * 8 + (lane >> 2)) * 36
                                     + kk + (lane & 3);
                b[nf][0] = __float_as_uint(pb[0]);
                b[nf][1] = __float_as_uint(pb[4]);
            }
        }
    };

    float acc[4][4][4];
    #pragma unroll
    for (int i = 0; i < 4; i++)
        #pragma unroll
        for (int j = 0; j < 4; j++)
            #pragma unroll
            for (int r = 0; r < 4; r++) acc[i][j][r] = 0.f;

    load_tile(0, 0);

    int cur = 0;
    for (int kt = 0; kt < NT; kt++) {
        if (kt + 1 < NT) {
            load_tile(cur ^ 1, (kt + 1) * 32);
            cpa_wait<1>();
        } else {
            cpa_wait<0>();
        }
        __syncthreads();

        const float* As = sm + cur * BUF;
        const float* Bs = As + AS;

        uint32_t a[2][4][4];
        uint32_t b[2][4][2];
        lfrag(As, Bs, 0, a[0], b[0]);

        #pragma unroll
        for (int ks = 0; ks < 4; ks++) {
            if (ks < 3) lfrag(As, Bs, ks + 1, a[(ks + 1) & 1], b[(ks + 1) & 1]);
            const uint32_t (*ac)[4] = a[ks & 1];
            const uint32_t (*bc)[2] = b[ks & 1];
            #pragma unroll
            for (int mf = 0; mf < 4; mf++)
                #pragma unroll
                for (int nf = 0; nf < 4; nf++)
                    mma_tf32(acc[mf][nf], ac[mf], bc[nf]);
        }
        __syncthreads();
        cur ^= 1;
    }

    // ---- epilogue ----
    const int crow = by * 128 + warp_m + (lane >> 2);
    const int ccol = bx * 128 + warp_n + ((lane & 3) << 1);
    #pragma unroll
    for (int mf = 0; mf < 4; mf++) {
        #pragma unroll
        for (int nf = 0; nf < 4; nf++) {
            float o0 = acc[mf][nf][0] * alpha, o1 = acc[mf][nf][1] * alpha;
            float o2 = acc[mf][nf][2] * alpha, o3 = acc[mf][nf][3] * alpha;
            if (ROUND_OUT) { o0 = rtf(o0); o1 = rtf(o1); o2 = rtf(o2); o3 = rtf(o3); }
            *(float2*)(C + (size_t)(crow + mf * 16)     * ldc + ccol + nf * 8) = make_float2(o0, o1);
            *(float2*)(C + (size_t)(crow + mf * 16 + 8) * ldc + ccol + nf * 8) = make_float2(o2, o3);
        }
    }
}

// ---------------------------------------------------------------------------
// Row softmax over S[SEQ][SEQ] in place; output tf32-rounded (consumed by PV).
// One block per row, 256 threads.
// ---------------------------------------------------------------------------
__global__ __launch_bounds__(256)
void softmax_kernel(float* __restrict__ S)
{
    constexpr int T = 256;
    constexpr int NV = SEQ / 4 / T;
    __shared__ float red[8];
    __shared__ float bcast;

    const int tid = threadIdx.x;
    float4* p = (float4*)(S + (size_t)blockIdx.x * SEQ);

    float4 v[NV];
    float mx = -INFINITY;
    #pragma unroll
    for (int i = 0; i < NV; i++) {
        v[i] = p[tid + i * T];
        mx = fmaxf(mx, fmaxf(fmaxf(v[i].x, v[i].y), fmaxf(v[i].z, v[i].w)));
    }
    #pragma unroll
    for (int o = 16; o; o >>= 1) mx = fmaxf(mx, __shfl_xor_sync(0xffffffffu, mx, o));
    if ((tid & 31) == 0) red[tid >> 5] = mx;
    __syncthreads();
    if (tid == 0) {
        float m = red[0];
        #pragma unroll
        for (int i = 1; i < 8; i++) m = fmaxf(m, red[i]);
        bcast = m;
    }
    __syncthreads();
    mx = bcast;

    float sum = 0.f;
    #pragma unroll
    for (int i = 0; i < NV; i++) {
        v[i].x = __expf(v[i].x - mx);
        v[i].y = __expf(v[i].y - mx);
        v[i].z = __expf(v[i].z - mx);
        v[i].w = __expf(v[i].w - mx);
        sum += (v[i].x + v[i].y) + (v[i].z + v[i].w);
    }
    #pragma unroll
    for (int o = 16; o; o >>= 1) sum += __shfl_xor_sync(0xffffffffu, sum, o);
    __syncthreads();
    if ((tid & 31) == 0) red[tid >> 5] = sum;
    __syncthreads();
    if (tid == 0) {
        float s = 0.f;
        #pragma unroll
        for (int i = 0; i < 8; i++) s += red[i];
        bcast = 1.f / s;
    }
    __syncthreads();
    const float inv = bcast;

    #pragma unroll
    for (int i = 0; i < NV; i++) {
        v[i].x = rtf(v[i].x * inv);
        v[i].y = rtf(v[i].y * inv);
        v[i].z = rtf(v[i].z * inv);
        v[i].w = rtf(v[i].w * inv);
        p[tid + i * T] = v[i];
    }
}

// ---------------------------------------------------------------------------
extern "C" void kernel_launch(void* const* d_in, const int* in_sizes, int n_in,
                              void* d_out, int out_size)
{
    const float* E  = (const float*)d_in[0];   // [SEQ, DMODEL]
    const float* Wq = (const float*)d_in[1];   // [DMODEL, DMODEL]
    const float* Wk = (const float*)d_in[2];
    const float* Wv = (const float*)d_in[3];
    float* out = (float*)d_out;                // [SEQ, DMODEL]

    float *Ep, *W, *QKV, *S;
    cudaGetSymbolAddress((void**)&Ep,  g_E);
    cudaGetSymbolAddress((void**)&W,   g_W);
    cudaGetSymbolAddress((void**)&QKV, g_QKV);
    cudaGetSymbolAddress((void**)&S,   g_S);

    constexpr int SMEM_NN = 2 * (128 * 36 + 32 * 136) * 4;   // 71680
    constexpr int SMEM_NT = 2 * (128 * 36 + 128 * 36) * 4;   // 73728
    cudaFuncSetAttribute(tf32_gemm<false, true>,
                         cudaFuncAttributeMaxDynamicSharedMemorySize, SMEM_NN);
    cudaFuncSetAttribute(tf32_gemm<false, false>,
                         cudaFuncAttributeMaxDynamicSharedMemorySize, SMEM_NN);
    cudaFuncSetAttribute(tf32_gemm<true, false>,
                         cudaFuncAttributeMaxDynamicSharedMemorySize, SMEM_NT);

    dim3 blk(256);

    // ---- prepass: tf32-round E; round+concat Wq|Wk|Wv ----
    round_copy4<<<(SEQ * DMODEL / 4 + 255) / 256, blk>>>((const float4*)E, (float4*)Ep,
                                                          SEQ * DMODEL / 4);
    round_concat_w<<<DMODEL * DMODEL / 4 / 256, blk>>>(Wq, W + 0 * DMODEL);
    round_concat_w<<<DMODEL * DMODEL / 4 / 256, blk>>>(Wk, W + 1 * DMODEL);
    round_concat_w<<<DMODEL * DMODEL / 4 / 256, blk>>>(Wv, W + 2 * DMODEL);

    // ---- fused QKV projection: [4096,3072] = E @ [Wq|Wk|Wv], round outputs ----
    dim3 gqkv(DQKV / 128, SEQ / 128);
    tf32_gemm<false, true><<<gqkv, blk, SMEM_NN>>>(Ep, DMODEL, W, DQKV,
                                                   QKV, DQKV, DMODEL, 1.0f);

    const float* Q = QKV + 0 * DMODEL;
    const float* Kp = QKV + 1 * DMODEL;
    const float* V = QKV + 2 * DMODEL;

    // ---- scores: S = (Q @ K^T) / 32 ----
    dim3 gs(SEQ / 128, SEQ / 128);
    tf32_gemm<true, false><<<gs, blk, SMEM_NT>>>(Q, DQKV, Kp, DQKV,
                                                 S, SEQ, DMODEL, 0.03125f);

    // ---- row softmax (in place, rounds P to tf32) ----
    softmax_kernel<<<SEQ, blk>>>(S);

    // ---- out = P @ V ----
    dim3 go(DMODEL / 128, SEQ / 128);
    tf32_gemm<false, false><<<go, blk, SMEM_NN>>>(S, SEQ, V, DQKV,
                                                  out, DMODEL, SEQ, 1.0f);
}

// round 9
// speedup vs baseline: 4.1739x; 1.3222x over previous
#include <cuda_runtime.h>
#include <math.h>
#include <stdint.h>

#define SEQ 4096
#define DMODEL 1024
#define DQKV 3072

// Scratch (allocation-free rule: __device__ globals)
__device__ float g_E[(size_t)SEQ * DMODEL];      // tf32-rounded E        [4096,1024]
__device__ float g_W[(size_t)DQKV * DMODEL];     // tf32-rounded W^T      [3072,1024] (n,k)
__device__ float g_QKV[(size_t)SEQ * DQKV];      // Q|K|V (tf32-rounded)  [4096,3072]
__device__ float g_Vt[(size_t)DMODEL * SEQ];     // V^T                   [1024,4096]
__device__ float g_S[(size_t)SEQ * SEQ];         // scores / probs        [4096,4096]

// ---------------------------------------------------------------------------
// helpers
// ---------------------------------------------------------------------------
__device__ __forceinline__ float rtf(float x) {
    uint32_t r;
    asm("cvt.rna.tf32.f32 %0, %1;" : "=r"(r) : "f"(x));
    return __uint_as_float(r);
}

__device__ __forceinline__ void cpa16(void* s, const void* g) {
    uint32_t sa = (uint32_t)__cvta_generic_to_shared(s);
    asm volatile("cp.async.cg.shared.global [%0], [%1], 16;" :: "r"(sa), "l"(g));
}
__device__ __forceinline__ void cpa_commit() { asm volatile("cp.async.commit_group;"); }
template <int N>
__device__ __forceinline__ void cpa_wait() { asm volatile("cp.async.wait_group %0;" :: "n"(N)); }

// ldmatrix x4 (b16 view; tf32 = 2 adjacent b16, no .trans so values intact)
__device__ __forceinline__ void ldsm_x4(uint32_t addr, uint32_t r[4]) {
    asm volatile("ldmatrix.sync.aligned.m8n8.x4.shared.b16 {%0,%1,%2,%3}, [%4];"
                 : "=r"(r[0]), "=r"(r[1]), "=r"(r[2]), "=r"(r[3]) : "r"(addr));
}

__device__ __forceinline__ void mma_tf32(float c[4], const uint32_t a[4], const uint32_t b[2]) {
    asm volatile(
        "mma.sync.aligned.m16n8k8.row.col.f32.tf32.tf32.f32 "
        "{%0,%1,%2,%3}, {%4,%5,%6,%7}, {%8,%9}, {%0,%1,%2,%3};"
        : "+f"(c[0]), "+f"(c[1]), "+f"(c[2]), "+f"(c[3])
        : "r"(a[0]), "r"(a[1]), "r"(a[2]), "r"(a[3]), "r"(b[0]), "r"(b[1]));
}

// ---------------------------------------------------------------------------
// Prepasses
// ---------------------------------------------------------------------------
__global__ void round_copy4(const float4* __restrict__ src, float4* __restrict__ dst, int n4)
{
    int i = blockIdx.x * blockDim.x + threadIdx.x;
    if (i < n4) {
        float4 v = src[i];
        v.x = rtf(v.x); v.y = rtf(v.y); v.z = rtf(v.z); v.w = rtf(v.w);
        dst[i] = v;
    }
}

// Transpose src[R,C] (ld=lds) -> dst[C,R] (ld=ldd); optional tf32 rounding.
template <bool RND>
__global__ __launch_bounds__(256)
void transpose_k(const float* __restrict__ src, int lds,
                 float* __restrict__ dst, int ldd)
{
    __shared__ float t[32][33];
    const int tx = threadIdx.x & 7;
    const int ty = threadIdx.x >> 3;
    const int r0 = blockIdx.y * 32, c0 = blockIdx.x * 32;

    float4 v = *(const float4*)(src + (size_t)(r0 + ty) * lds + c0 + tx * 4);
    if (RND) { v.x = rtf(v.x); v.y = rtf(v.y); v.z = rtf(v.z); v.w = rtf(v.w); }
    t[ty][tx * 4 + 0] = v.x; t[ty][tx * 4 + 1] = v.y;
    t[ty][tx * 4 + 2] = v.z; t[ty][tx * 4 + 3] = v.w;
    __syncthreads();

    float4 o;
    o.x = t[tx * 4 + 0][ty]; o.y = t[tx * 4 + 1][ty];
    o.z = t[tx * 4 + 2][ty]; o.w = t[tx * 4 + 3][ty];
    *(float4*)(dst + (size_t)(c0 + ty) * ldd + r0 + tx * 4) = o;
}

// ---------------------------------------------------------------------------
// TF32 mma.sync GEMM (NT): C[M,N] = alpha * A[M,K] @ B[N,K]^T, row-major,
// operands pre-rounded to tf32. CTA tile 128x128, K-tile 32 (128B SW128 rows).
// 256 threads / 8 warps, warp tile 64x32. Fragments via ldmatrix.x4.
// 3-stage cp.async pipeline, 1 __syncthreads per k-tile.
// ---------------------------------------------------------------------------
template <bool ROUND_OUT>
__global__ __launch_bounds__(256, 2)
void tc_gemm(const float* __restrict__ A, int lda,
             const float* __restrict__ B, int ldb,
             float* __restrict__ C, int ldc,
             int K, float alpha)
{
    extern __shared__ char smem[];
    const uint32_t sbase = (uint32_t)__cvta_generic_to_shared(smem);

    const int tid  = threadIdx.x;
    const int lane = tid & 31;
    const int wid  = tid >> 5;
    const int warp_m = (wid & 1) * 64;
    const int warp_n = (wid >> 1) * 32;
    const int bx = blockIdx.x, by = blockIdx.y;
    const int NT = K / 32;

    const float* Arow = A + (size_t)(by * 128) * lda;
    const float* Brow = B + (size_t)(bx * 128) * ldb;

    // stage = 32KB: A tile 16KB (128 rows x 128B) | B tile 16KB
    auto load_tile = [&](int buf, int kt) {
        const int k0 = kt * 32;
        char* st = smem + buf * 32768;
        #pragma unroll
        for (int l = 0; l < 4; l++) {
            int c = tid + l * 256;
            int row = c >> 3, ch = c & 7;
            uint32_t off = (uint32_t)(row * 128 + ((ch * 16) ^ ((row & 7) << 4)));
            cpa16(st + off, Arow + (size_t)row * lda + k0 + ch * 4);
        }
        #pragma unroll
        for (int l = 0; l < 4; l++) {
            int c = tid + l * 256;
            int row = c >> 3, ch = c & 7;
            uint32_t off = (uint32_t)(row * 128 + ((ch * 16) ^ ((row & 7) << 4)));
            cpa16(st + 16384 + off, Brow + (size_t)row * ldb + k0 + ch * 4);
        }
        cpa_commit();
    };

    // ldmatrix per-lane address components (swizzle mask = (lane&7)<<4, since
    // all row bases are multiples of 8)
    const uint32_t xmask = (uint32_t)((lane & 7) << 4);
    // A: quadrants = {mblk0,k0},{mblk1,k0},{mblk0,k1},{mblk1,k1}
    const int a_row = warp_m + (lane & 7) + ((lane >> 3) & 1) * 8;
    const uint32_t a_kh = (uint32_t)((lane >> 4) * 16);
    // B: quadrants = {nf_even,k0},{nf_even,k1},{nf_odd,k0},{nf_odd,k1}
    const int b_row = warp_n + (lane & 7) + ((lane >> 4) & 1) * 8;
    const uint32_t b_kh = (uint32_t)(((lane >> 3) & 1) * 16);

    const uint32_t a_base = sbase + (uint32_t)(a_row * 128);
    const uint32_t b_base = sbase + 16384u + (uint32_t)(b_row * 128);

    auto lfrag = [&](uint32_t soff, int ks, uint32_t a[4][4], uint32_t b[2][4]) {
        const uint32_t ka = ((uint32_t)(ks * 32) + a_kh) ^ xmask;
        const uint32_t kb = ((uint32_t)(ks * 32) + b_kh) ^ xmask;
        #pragma unroll
        for (int mf = 0; mf < 4; mf++)
            ldsm_x4(a_base + soff + (uint32_t)(mf * 2048) + ka, a[mf]);
        #pragma unroll
        for (int pr = 0; pr < 2; pr++)
            ldsm_x4(b_base + soff + (uint32_t)(pr * 2048) + kb, b[pr]);
    };

    float acc[4][4][4];
    #pragma unroll
    for (int i = 0; i < 4; i++)
        #pragma unroll
        for (int j = 0; j < 4; j++)
            #pragma unroll
            for (int r = 0; r < 4; r++) acc[i][j][r] = 0.f;

    load_tile(0, 0);
    load_tile(1, 1);

    for (int kt = 0; kt < NT; kt++) {
        if (kt + 1 < NT) cpa_wait<1>(); else cpa_wait<0>();
        __syncthreads();                       // tile kt ready; all warps past kt-1
        if (kt + 2 < NT) load_tile((kt + 2) % 3, kt + 2);

        const uint32_t soff = (uint32_t)((kt % 3) * 32768);

        uint32_t a[2][4][4];
        uint32_t b[2][2][4];
        lfrag(soff, 0, a[0], b[0]);

        #pragma unroll
        for (int ks = 0; ks < 4; ks++) {
            if (ks < 3) lfrag(soff, ks + 1, a[(ks + 1) & 1], b[(ks + 1) & 1]);
            const uint32_t (*ac)[4] = a[ks & 1];
            const uint32_t (*bc)[4] = b[ks & 1];
            #pragma unroll
            for (int mf = 0; mf < 4; mf++)
                #pragma unroll
                for (int nf = 0; nf < 4; nf++)
                    mma_tf32(acc[mf][nf], ac[mf], &bc[nf >> 1][(nf & 1) * 2]);
        }
    }

    // ---- epilogue ----
    const int crow = by * 128 + warp_m + (lane >> 2);
    const int ccol = bx * 128 + warp_n + ((lane & 3) << 1);
    #pragma unroll
    for (int mf = 0; mf < 4; mf++) {
        #pragma unroll
        for (int nf = 0; nf < 4; nf++) {
            float o0 = acc[mf][nf][0] * alpha, o1 = acc[mf][nf][1] * alpha;
            float o2 = acc[mf][nf][2] * alpha, o3 = acc[mf][nf][3] * alpha;
            if (ROUND_OUT) { o0 = rtf(o0); o1 = rtf(o1); o2 = rtf(o2); o3 = rtf(o3); }
            *(float2*)(C + (size_t)(crow + mf * 16)     * ldc + ccol + nf * 8) = make_float2(o0, o1);
            *(float2*)(C + (size_t)(crow + mf * 16 + 8) * ldc + ccol + nf * 8) = make_float2(o2, o3);
        }
    }
}

// ---------------------------------------------------------------------------
// Row softmax over S[SEQ][SEQ] in place; output tf32-rounded.
// ---------------------------------------------------------------------------
__global__ __launch_bounds__(256)
void softmax_kernel(float* __restrict__ S)
{
    constexpr int T = 256;
    constexpr int NV = SEQ / 4 / T;
    __shared__ float red[8];
    __shared__ float bcast;

    const int tid = threadIdx.x;
    float4* p = (float4*)(S + (size_t)blockIdx.x * SEQ);

    float4 v[NV];
    float mx = -INFINITY;
    #pragma unroll
    for (int i = 0; i < NV; i++) {
        v[i] = p[tid + i * T];
        mx = fmaxf(mx, fmaxf(fmaxf(v[i].x, v[i].y), fmaxf(v[i].z, v[i].w)));
    }
    #pragma unroll
    for (int o = 16; o; o >>= 1) mx = fmaxf(mx, __shfl_xor_sync(0xffffffffu, mx, o));
    if ((tid & 31) == 0) red[tid >> 5] = mx;
    __syncthreads();
    if (tid == 0) {
        float m = red[0];
        #pragma unroll
        for (int i = 1; i < 8; i++) m = fmaxf(m, red[i]);
        bcast = m;
    }
    __syncthreads();
    mx = bcast;

    float sum = 0.f;
    #pragma unroll
    for (int i = 0; i < NV; i++) {
        v[i].x = __expf(v[i].x - mx);
        v[i].y = __expf(v[i].y - mx);
        v[i].z = __expf(v[i].z - mx);
        v[i].w = __expf(v[i].w - mx);
        sum += (v[i].x + v[i].y) + (v[i].z + v[i].w);
    }
    #pragma unroll
    for (int o = 16; o; o >>= 1) sum += __shfl_xor_sync(0xffffffffu, sum, o);
    __syncthreads();
    if ((tid & 31) == 0) red[tid >> 5] = sum;
    __syncthreads();
    if (tid == 0) {
        float s = 0.f;
        #pragma unroll
        for (int i = 0; i < 8; i++) s += red[i];
        bcast = 1.f / s;
    }
    __syncthreads();
    const float inv = bcast;

    #pragma unroll
    for (int i = 0; i < NV; i++) {
        v[i].x = rtf(v[i].x * inv);
        v[i].y = rtf(v[i].y * inv);
        v[i].z = rtf(v[i].z * inv);
        v[i].w = rtf(v[i].w * inv);
        p[tid + i * T] = v[i];
    }
}

// ---------------------------------------------------------------------------
extern "C" void kernel_launch(void* const* d_in, const int* in_sizes, int n_in,
                              void* d_out, int out_size)
{
    const float* E  = (const float*)d_in[0];
    const float* Wq = (const float*)d_in[1];
    const float* Wk = (const float*)d_in[2];
    const float* Wv = (const float*)d_in[3];
    float* out = (float*)d_out;

    float *Ep, *Wt, *QKV, *Vt, *S;
    cudaGetSymbolAddress((void**)&Ep,  g_E);
    cudaGetSymbolAddress((void**)&Wt,  g_W);
    cudaGetSymbolAddress((void**)&QKV, g_QKV);
    cudaGetSymbolAddress((void**)&Vt,  g_Vt);
    cudaGetSymbolAddress((void**)&S,   g_S);

    constexpr int SMEM_BYTES = 3 * 32768;   // 98304
    cudaFuncSetAttribute(tc_gemm<true>,
                         cudaFuncAttributeMaxDynamicSharedMemorySize, SMEM_BYTES);
    cudaFuncSetAttribute(tc_gemm<false>,
                         cudaFuncAttributeMaxDynamicSharedMemorySize, SMEM_BYTES);

    dim3 blk(256);

    // prepass: round E; round+transpose Wq|Wk|Wv -> Wt [3072,1024]
    round_copy4<<<SEQ * DMODEL / 4 / 256, blk>>>((const float4*)E, (float4*)Ep,
                                                 SEQ * DMODEL / 4);
    dim3 gt(32, 32);
    transpose_k<true><<<gt, blk>>>(Wq, DMODEL, Wt + 0 * DMODEL * DMODEL, DMODEL);
    transpose_k<true><<<gt, blk>>>(Wk, DMODEL, Wt + 1 * DMODEL * DMODEL, DMODEL);
    transpose_k<true><<<gt, blk>>>(Wv, DMODEL, Wt + 2 * DMODEL * DMODEL, DMODEL);

    // QKV: [4096,3072] = E @ Wt^T (round outputs)
    tc_gemm<true><<<dim3(DQKV / 128, SEQ / 128), blk, SMEM_BYTES>>>(
        Ep, DMODEL, Wt, DMODEL, QKV, DQKV, DMODEL, 1.0f);

    const float* Q  = QKV;
    const float* Kp = QKV + DMODEL;
    const float* V  = QKV + 2 * DMODEL;

    // V^T: [1024,4096] (already rounded)
    transpose_k<false><<<dim3(DMODEL / 32, SEQ / 32), blk>>>(V, DQKV, Vt, SEQ);

    // S = (Q @ K^T) / 32
    tc_gemm<false><<<dim3(SEQ / 128, SEQ / 128), blk, SMEM_BYTES>>>(
        Q, DQKV, Kp, DQKV, S, SEQ, DMODEL, 0.03125f);

    // softmax (rounds P)
    softmax_kernel<<<SEQ, blk>>>(S);

    // out = P @ (V^T)^T
    tc_gemm<false><<<dim3(DMODEL / 128, SEQ / 128), blk, SMEM_BYTES>>>(
        S, SEQ, Vt, SEQ, out, DMODEL, SEQ, 1.0f);
}

// round 10
// speedup vs baseline: 4.2062x; 1.0077x over previous
#include <cuda_runtime.h>
#include <math.h>
#include <stdint.h>

#define SEQ 4096
#define DMODEL 1024
#define DQKV 3072

// Scratch (allocation-free rule: __device__ globals)
__device__ float g_E[(size_t)SEQ * DMODEL];      // tf32-rounded E        [4096,1024]
__device__ float g_W[(size_t)DQKV * DMODEL];     // tf32-rounded W^T      [3072,1024] (n,k)
__device__ float g_QKV[(size_t)SEQ * DQKV];      // Q|K|V (tf32-rounded)  [4096,3072]
__device__ float g_Vt[(size_t)DMODEL * SEQ];     // V^T                   [1024,4096]
__device__ float g_S[(size_t)SEQ * SEQ];         // scores / probs        [4096,4096]

// ---------------------------------------------------------------------------
// helpers
// ---------------------------------------------------------------------------
__device__ __forceinline__ float rtf(float x) {
    uint32_t r;
    asm("cvt.rna.tf32.f32 %0, %1;" : "=r"(r) : "f"(x));
    return __uint_as_float(r);
}

__device__ __forceinline__ void cpa16(void* s, const void* g) {
    uint32_t sa = (uint32_t)__cvta_generic_to_shared(s);
    asm volatile("cp.async.cg.shared.global [%0], [%1], 16;" :: "r"(sa), "l"(g));
}
__device__ __forceinline__ void cpa_commit() { asm volatile("cp.async.commit_group;"); }
template <int N>
__device__ __forceinline__ void cpa_wait() { asm volatile("cp.async.wait_group %0;" :: "n"(N)); }

// ldmatrix x4 (b16 view; tf32 = 2 adjacent b16, no .trans so values intact)
__device__ __forceinline__ void ldsm_x4(uint32_t addr, uint32_t r[4]) {
    asm volatile("ldmatrix.sync.aligned.m8n8.x4.shared.b16 {%0,%1,%2,%3}, [%4];"
                 : "=r"(r[0]), "=r"(r[1]), "=r"(r[2]), "=r"(r[3]) : "r"(addr));
}

__device__ __forceinline__ void mma_tf32(float c[4], const uint32_t a[4], const uint32_t b[2]) {
    asm volatile(
        "mma.sync.aligned.m16n8k8.row.col.f32.tf32.tf32.f32 "
        "{%0,%1,%2,%3}, {%4,%5,%6,%7}, {%8,%9}, {%0,%1,%2,%3};"
        : "+f"(c[0]), "+f"(c[1]), "+f"(c[2]), "+f"(c[3])
        : "r"(a[0]), "r"(a[1]), "r"(a[2]), "r"(a[3]), "r"(b[0]), "r"(b[1]));
}

// ---------------------------------------------------------------------------
// Prepasses
// ---------------------------------------------------------------------------
__global__ void round_copy4(const float4* __restrict__ src, float4* __restrict__ dst, int n4)
{
    int i = blockIdx.x * blockDim.x + threadIdx.x;
    if (i < n4) {
        float4 v = src[i];
        v.x = rtf(v.x); v.y = rtf(v.y); v.z = rtf(v.z); v.w = rtf(v.w);
        dst[i] = v;
    }
}

// Transpose src[R,C] (ld=lds) -> dst[C,R] (ld=ldd); optional tf32 rounding.
template <bool RND>
__global__ __launch_bounds__(256)
void transpose_k(const float* __restrict__ src, int lds,
                 float* __restrict__ dst, int ldd)
{
    __shared__ float t[32][33];
    const int tx = threadIdx.x & 7;
    const int ty = threadIdx.x >> 3;
    const int r0 = blockIdx.y * 32, c0 = blockIdx.x * 32;

    float4 v = *(const float4*)(src + (size_t)(r0 + ty) * lds + c0 + tx * 4);
    if (RND) { v.x = rtf(v.x); v.y = rtf(v.y); v.z = rtf(v.z); v.w = rtf(v.w); }
    t[ty][tx * 4 + 0] = v.x; t[ty][tx * 4 + 1] = v.y;
    t[ty][tx * 4 + 2] = v.z; t[ty][tx * 4 + 3] = v.w;
    __syncthreads();

    float4 o;
    o.x = t[tx * 4 + 0][ty]; o.y = t[tx * 4 + 1][ty];
    o.z = t[tx * 4 + 2][ty]; o.w = t[tx * 4 + 3][ty];
    *(float4*)(dst + (size_t)(c0 + ty) * ldd + r0 + tx * 4) = o;
}

// Merged W transpose: z selects Wq/Wk/Wv -> Wt band; always rounds.
__global__ __launch_bounds__(256)
void transpose_w3(const float* __restrict__ w0, const float* __restrict__ w1,
                  const float* __restrict__ w2, float* __restrict__ dst)
{
    __shared__ float t[32][33];
    const int tx = threadIdx.x & 7;
    const int ty = threadIdx.x >> 3;
    const int r0 = blockIdx.y * 32, c0 = blockIdx.x * 32;
    const float* src = (blockIdx.z == 0) ? w0 : (blockIdx.z == 1) ? w1 : w2;
    float* d = dst + (size_t)blockIdx.z * DMODEL * DMODEL;

    float4 v = *(const float4*)(src + (size_t)(r0 + ty) * DMODEL + c0 + tx * 4);
    v.x = rtf(v.x); v.y = rtf(v.y); v.z = rtf(v.z); v.w = rtf(v.w);
    t[ty][tx * 4 + 0] = v.x; t[ty][tx * 4 + 1] = v.y;
    t[ty][tx * 4 + 2] = v.z; t[ty][tx * 4 + 3] = v.w;
    __syncthreads();

    float4 o;
    o.x = t[tx * 4 + 0][ty]; o.y = t[tx * 4 + 1][ty];
    o.z = t[tx * 4 + 2][ty]; o.w = t[tx * 4 + 3][ty];
    *(float4*)(d + (size_t)(c0 + ty) * DMODEL + r0 + tx * 4) = o;
}

// ---------------------------------------------------------------------------
// TF32 mma.sync GEMM (NT): C[M,N] = alpha * A[M,K] @ B[N,K]^T, row-major,
// operands pre-rounded to tf32. CTA tile 128x128, K-tile 32 (128B SW128 rows).
// 128 threads / 4 warps, warp tile 64x64 (CUTLASS-canonical). Fragments via
// ldmatrix.x4, double-buffered. 3-stage cp.async pipeline, 1 sync per k-tile.
// ---------------------------------------------------------------------------
template <bool ROUND_OUT>
__global__ __launch_bounds__(128, 2)
void tc_gemm(const float* __restrict__ A, int lda,
             const float* __restrict__ B, int ldb,
             float* __restrict__ C, int ldc,
             int K, float alpha)
{
    extern __shared__ char smem[];
    const uint32_t sbase = (uint32_t)__cvta_generic_to_shared(smem);

    const int tid  = threadIdx.x;
    const int lane = tid & 31;
    const int wid  = tid >> 5;           // 0..3
    const int warp_m = (wid & 1) * 64;
    const int warp_n = (wid >> 1) * 64;
    const int bx = blockIdx.x, by = blockIdx.y;
    const int NT = K / 32;

    const float* Arow = A + (size_t)(by * 128) * lda;
    const float* Brow = B + (size_t)(bx * 128) * ldb;

    // stage = 32KB: A tile 16KB (128 rows x 128B) | B tile 16KB
    auto load_tile = [&](int buf, int kt) {
        const int k0 = kt * 32;
        char* st = smem + buf * 32768;
        #pragma unroll
        for (int l = 0; l < 8; l++) {
            int c = tid + l * 128;
            int row = c >> 3, ch = c & 7;
            uint32_t off = (uint32_t)(row * 128 + ((ch * 16) ^ ((row & 7) << 4)));
            cpa16(st + off, Arow + (size_t)row * lda + k0 + ch * 4);
        }
        #pragma unroll
        for (int l = 0; l < 8; l++) {
            int c = tid + l * 128;
            int row = c >> 3, ch = c & 7;
            uint32_t off = (uint32_t)(row * 128 + ((ch * 16) ^ ((row & 7) << 4)));
            cpa16(st + 16384 + off, Brow + (size_t)row * ldb + k0 + ch * 4);
        }
        cpa_commit();
    };

    // ldmatrix per-lane address components (swizzle mask = (lane&7)<<4; row
    // bases are multiples of 8 so the mask commutes with the row offset)
    const uint32_t xmask = (uint32_t)((lane & 7) << 4);
    // A quadrants: {mblk0,k0},{mblk1,k0},{mblk0,k1},{mblk1,k1}
    const int a_row = warp_m + (lane & 7) + ((lane >> 3) & 1) * 8;
    const uint32_t a_kh = (uint32_t)((lane >> 4) * 16);
    // B quadrants: {nf_even,k0},{nf_even,k1},{nf_odd,k0},{nf_odd,k1}
    const int b_row = warp_n + (lane & 7) + ((lane >> 4) & 1) * 8;
    const uint32_t b_kh = (uint32_t)(((lane >> 3) & 1) * 16);

    const uint32_t a_base = sbase + (uint32_t)(a_row * 128);
    const uint32_t b_base = sbase + 16384u + (uint32_t)(b_row * 128);

    // a[4][4]: 64 M-rows; b[4][4]: 64 N-cols (pr covers 16 cols each)
    auto lfrag = [&](uint32_t soff, int ks, uint32_t a[4][4], uint32_t b[4][4]) {
        const uint32_t ka = ((uint32_t)(ks * 32) + a_kh) ^ xmask;
        const uint32_t kb = ((uint32_t)(ks * 32) + b_kh) ^ xmask;
        #pragma unroll
        for (int mf = 0; mf < 4; mf++)
            ldsm_x4(a_base + soff + (uint32_t)(mf * 2048) + ka, a[mf]);
        #pragma unroll
        for (int pr = 0; pr < 4; pr++)
            ldsm_x4(b_base + soff + (uint32_t)(pr * 2048) + kb, b[pr]);
    };

    float acc[4][8][4];
    #pragma unroll
    for (int i = 0; i < 4; i++)
        #pragma unroll
        for (int j = 0; j < 8; j++)
            #pragma unroll
            for (int r = 0; r < 4; r++) acc[i][j][r] = 0.f;

    load_tile(0, 0);
    load_tile(1, 1);

    for (int kt = 0; kt < NT; kt++) {
        if (kt + 1 < NT) cpa_wait<1>(); else cpa_wait<0>();
        __syncthreads();                       // tile kt ready; all warps past kt-1
        if (kt + 2 < NT) load_tile((kt + 2) % 3, kt + 2);

        const uint32_t soff = (uint32_t)((kt % 3) * 32768);

        uint32_t a[2][4][4];
        uint32_t b[2][4][4];
        lfrag(soff, 0, a[0], b[0]);

        #pragma unroll
        for (int ks = 0; ks < 4; ks++) {
            if (ks < 3) lfrag(soff, ks + 1, a[(ks + 1) & 1], b[(ks + 1) & 1]);
            const uint32_t (*ac)[4] = a[ks & 1];
            const uint32_t (*bc)[4] = b[ks & 1];
            #pragma unroll
            for (int mf = 0; mf < 4; mf++)
                #pragma unroll
                for (int nf = 0; nf < 8; nf++)
                    mma_tf32(acc[mf][nf], ac[mf], &bc[nf >> 1][(nf & 1) * 2]);
        }
    }

    // ---- epilogue ----
    const int crow = by * 128 + warp_m + (lane >> 2);
    const int ccol = bx * 128 + warp_n + ((lane & 3) << 1);
    #pragma unroll
    for (int mf = 0; mf < 4; mf++) {
        #pragma unroll
        for (int nf = 0; nf < 8; nf++) {
            float o0 = acc[mf][nf][0] * alpha, o1 = acc[mf][nf][1] * alpha;
            float o2 = acc[mf][nf][2] * alpha, o3 = acc[mf][nf][3] * alpha;
            if (ROUND_OUT) { o0 = rtf(o0); o1 = rtf(o1); o2 = rtf(o2); o3 = rtf(o3); }
            *(float2*)(C + (size_t)(crow + mf * 16)     * ldc + ccol + nf * 8) = make_float2(o0, o1);
            *(float2*)(C + (size_t)(crow + mf * 16 + 8) * ldc + ccol + nf * 8) = make_float2(o2, o3);
        }
    }
}

// ---------------------------------------------------------------------------
// Row softmax over S[SEQ][SEQ] in place; output tf32-rounded.
// ---------------------------------------------------------------------------
__global__ __launch_bounds__(256)
void softmax_kernel(float* __restrict__ S)
{
    constexpr int T = 256;
    constexpr int NV = SEQ / 4 / T;
    __shared__ float red[8];
    __shared__ float bcast;

    const int tid = threadIdx.x;
    float4* p = (float4*)(S + (size_t)blockIdx.x * SEQ);

    float4 v[NV];
    float mx = -INFINITY;
    #pragma unroll
    for (int i = 0; i < NV; i++) {
        v[i] = p[tid + i * T];
        mx = fmaxf(mx, fmaxf(fmaxf(v[i].x, v[i].y), fmaxf(v[i].z, v[i].w)));
    }
    #pragma unroll
    for (int o = 16; o; o >>= 1) mx = fmaxf(mx, __shfl_xor_sync(0xffffffffu, mx, o));
    if ((tid & 31) == 0) red[tid >> 5] = mx;
    __syncthreads();
    if (tid == 0) {
        float m = red[0];
        #pragma unroll
        for (int i = 1; i < 8; i++) m = fmaxf(m, red[i]);
        bcast = m;
    }
    __syncthreads();
    mx = bcast;

    float sum = 0.f;
    #pragma unroll
    for (int i = 0; i < NV; i++) {
        v[i].x = __expf(v[i].x - mx);
        v[i].y = __expf(v[i].y - mx);
        v[i].z = __expf(v[i].z - mx);
        v[i].w = __expf(v[i].w - mx);
        sum += (v[i].x + v[i].y) + (v[i].z + v[i].w);
    }
    #pragma unroll
    for (int o = 16; o; o >>= 1) sum += __shfl_xor_sync(0xffffffffu, sum, o);
    __syncthreads();
    if ((tid & 31) == 0) red[tid >> 5] = sum;
    __syncthreads();
    if (tid == 0) {
        float s = 0.f;
        #pragma unroll
        for (int i = 0; i < 8; i++) s += red[i];
        bcast = 1.f / s;
    }
    __syncthreads();
    const float inv = bcast;

    #pragma unroll
    for (int i = 0; i < NV; i++) {
        v[i].x = rtf(v[i].x * inv);
        v[i].y = rtf(v[i].y * inv);
        v[i].z = rtf(v[i].z * inv);
        v[i].w = rtf(v[i].w * inv);
        p[tid + i * T] = v[i];
    }
}

// ---------------------------------------------------------------------------
extern "C" void kernel_launch(void* const* d_in, const int* in_sizes, int n_in,
                              void* d_out, int out_size)
{
    const float* E  = (const float*)d_in[0];
    const float* Wq = (const float*)d_in[1];
    const float* Wk = (const float*)d_in[2];
    const float* Wv = (const float*)d_in[3];
    float* out = (float*)d_out;

    float *Ep, *Wt, *QKV, *Vt, *S;
    cudaGetSymbolAddress((void**)&Ep,  g_E);
    cudaGetSymbolAddress((void**)&Wt,  g_W);
    cudaGetSymbolAddress((void**)&QKV, g_QKV);
    cudaGetSymbolAddress((void**)&Vt,  g_Vt);
    cudaGetSymbolAddress((void**)&S,   g_S);

    constexpr int SMEM_BYTES = 3 * 32768;   // 98304
    cudaFuncSetAttribute(tc_gemm<true>,
                         cudaFuncAttributeMaxDynamicSharedMemorySize, SMEM_BYTES);
    cudaFuncSetAttribute(tc_gemm<false>,
                         cudaFuncAttributeMaxDynamicSharedMemorySize, SMEM_BYTES);

    // prepass: round E; round+transpose Wq|Wk|Wv -> Wt [3072,1024] (one launch)
    round_copy4<<<SEQ * DMODEL / 4 / 256, 256>>>((const float4*)E, (float4*)Ep,
                                                 SEQ * DMODEL / 4);
    transpose_w3<<<dim3(32, 32, 3), 256>>>(Wq, Wk, Wv, Wt);

    dim3 blk(128);

    // QKV: [4096,3072] = E @ Wt^T (round outputs)
    tc_gemm<true><<<dim3(DQKV / 128, SEQ / 128), blk, SMEM_BYTES>>>(
        Ep, DMODEL, Wt, DMODEL, QKV, DQKV, DMODEL, 1.0f);

    const float* Q  = QKV;
    const float* Kp = QKV + DMODEL;
    const float* V  = QKV + 2 * DMODEL;

    // V^T: [1024,4096] (already rounded)
    transpose_k<false><<<dim3(DMODEL / 32, SEQ / 32), 256>>>(V, DQKV, Vt, SEQ);

    // S = (Q @ K^T) / 32
    tc_gemm<false><<<dim3(SEQ / 128, SEQ / 128), blk, SMEM_BYTES>>>(
        Q, DQKV, Kp, DQKV, S, SEQ, DMODEL, 0.03125f);

    // softmax (rounds P)
    softmax_kernel<<<SEQ, blk.x * 2>>>(S);

    // out = P @ (V^T)^T
    tc_gemm<false><<<dim3(DMODEL / 128, SEQ / 128), blk, SMEM_BYTES>>>(
        S, SEQ, Vt, SEQ, out, DMODEL, SEQ, 1.0f);
}

// round 12
// speedup vs baseline: 7.5662x; 1.7988x over previous
#include <cuda_runtime.h>
#include <cuda_fp16.h>
#include <math.h>
#include <stdint.h>

#define SEQ 4096
#define DMODEL 1024
#define DQKV 3072

// Scratch (allocation-free rule: __device__ globals)
__device__ __half g_Eh[(size_t)SEQ * DMODEL];     // fp16 E            [4096,1024]
__device__ __half g_Wh[(size_t)DQKV * DMODEL];    // fp16 W^T          [3072,1024] (n,k)
__device__ __half g_QKVh[(size_t)SEQ * DQKV];     // fp16 Q|K|V        [4096,3072]
__device__ __half g_Vth[(size_t)DMODEL * SEQ];    // fp16 V^T          [1024,4096]
__device__ float  g_S[(size_t)SEQ * SEQ];         // fp32 scores       [4096,4096]
__device__ __half g_P[(size_t)SEQ * SEQ];         // fp16 probs        [4096,4096]

// ---------------------------------------------------------------------------
// helpers
// ---------------------------------------------------------------------------
__device__ __forceinline__ void cpa16(void* s, const void* g) {
    uint32_t sa = (uint32_t)__cvta_generic_to_shared(s);
    asm volatile("cp.async.cg.shared.global [%0], [%1], 16;" :: "r"(sa), "l"(g));
}
__device__ __forceinline__ void cpa_commit() { asm volatile("cp.async.commit_group;"); }
template <int N>
__device__ __forceinline__ void cpa_wait() { asm volatile("cp.async.wait_group %0;" :: "n"(N)); }

__device__ __forceinline__ void ldsm_x4(uint32_t addr, uint32_t r[4]) {
    asm volatile("ldmatrix.sync.aligned.m8n8.x4.shared.b16 {%0,%1,%2,%3}, [%4];"
                 : "=r"(r[0]), "=r"(r[1]), "=r"(r[2]), "=r"(r[3]) : "r"(addr));
}

__device__ __forceinline__ void mma_f16(float c[4], const uint32_t a[4], const uint32_t b[2]) {
    asm volatile(
        "mma.sync.aligned.m16n8k16.row.col.f32.f16.f16.f32 "
        "{%0,%1,%2,%3}, {%4,%5,%6,%7}, {%8,%9}, {%0,%1,%2,%3};"
        : "+f"(c[0]), "+f"(c[1]), "+f"(c[2]), "+f"(c[3])
        : "r"(a[0]), "r"(a[1]), "r"(a[2]), "r"(a[3]), "r"(b[0]), "r"(b[1]));
}

// paired store: fp32 or fp16 (rounds here)
__device__ __forceinline__ void st2(float* p, float x, float y) {
    *(float2*)p = make_float2(x, y);
}
__device__ __forceinline__ void st2(__half* p, float x, float y) {
    *(__half2*)p = __floats2half2_rn(x, y);
}

// ---------------------------------------------------------------------------
// Prepasses
// ---------------------------------------------------------------------------
__global__ void f2h_copy(const float4* __restrict__ src, __half2* __restrict__ dst, int n4)
{
    int i = blockIdx.x * blockDim.x + threadIdx.x;
    if (i < n4) {
        float4 v = src[i];
        dst[2 * i + 0] = __floats2half2_rn(v.x, v.y);
        dst[2 * i + 1] = __floats2half2_rn(v.z, v.w);
    }
}

// Merged W transpose: z selects Wq/Wk/Wv; fp32 in -> fp16 out (transposed).
__global__ __launch_bounds__(256)
void transpose_w3(const float* __restrict__ w0, const float* __restrict__ w1,
                  const float* __restrict__ w2, __half* __restrict__ dst)
{
    __shared__ float t[32][33];
    const int tx = threadIdx.x & 7;
    const int ty = threadIdx.x >> 3;
    const int r0 = blockIdx.y * 32, c0 = blockIdx.x * 32;
    const float* src = (blockIdx.z == 0) ? w0 : (blockIdx.z == 1) ? w1 : w2;
    __half* d = dst + (size_t)blockIdx.z * DMODEL * DMODEL;

    float4 v = *(const float4*)(src + (size_t)(r0 + ty) * DMODEL + c0 + tx * 4);
    t[ty][tx * 4 + 0] = v.x; t[ty][tx * 4 + 1] = v.y;
    t[ty][tx * 4 + 2] = v.z; t[ty][tx * 4 + 3] = v.w;
    __syncthreads();

    __half* o = d + (size_t)(c0 + ty) * DMODEL + r0 + tx * 4;
    *(__half2*)(o + 0) = __floats2half2_rn(t[tx * 4 + 0][ty], t[tx * 4 + 1][ty]);
    *(__half2*)(o + 2) = __floats2half2_rn(t[tx * 4 + 2][ty], t[tx * 4 + 3][ty]);
}

// fp16 transpose: src[R,C] (ld=lds) -> dst[C,R] (ld=ldd)
__global__ __launch_bounds__(256)
void transpose_h(const __half* __restrict__ src, int lds,
                 __half* __restrict__ dst, int ldd)
{
    __shared__ float t[32][33];
    const int tx = threadIdx.x & 7;
    const int ty = threadIdx.x >> 3;
    const int r0 = blockIdx.y * 32, c0 = blockIdx.x * 32;

    const __half* s = src + (size_t)(r0 + ty) * lds + c0 + tx * 4;
    __half2 h0 = *(const __half2*)(s + 0);
    __half2 h1 = *(const __half2*)(s + 2);
    t[ty][tx * 4 + 0] = __low2float(h0);  t[ty][tx * 4 + 1] = __high2float(h0);
    t[ty][tx * 4 + 2] = __low2float(h1);  t[ty][tx * 4 + 3] = __high2float(h1);
    __syncthreads();

    __half* o = dst + (size_t)(c0 + ty) * ldd + r0 + tx * 4;
    *(__half2*)(o + 0) = __floats2half2_rn(t[tx * 4 + 0][ty], t[tx * 4 + 1][ty]);
    *(__half2*)(o + 2) = __floats2half2_rn(t[tx * 4 + 2][ty], t[tx * 4 + 3][ty]);
}

// ---------------------------------------------------------------------------
// FP16 mma.sync GEMM (NT): C[M,N] = alpha * A[M,K] @ B[N,K]^T.
// A,B fp16 row-major (K-major); C fp32 or fp16 (OutT). fp32 accumulate.
// CTA tile 128x128, K-tile 64 halves (128B SW-swizzled rows). 128 threads /
// 4 warps, warp tile 64x64. m16n8k16 fragments via ldmatrix.x4 (same lane
// quadrant mapping as the validated tf32 version). 3-stage cp.async pipeline,
// fragment double-buffering across the 4 k16-steps per tile.
// ---------------------------------------------------------------------------
template <typename OutT>
__global__ __launch_bounds__(128, 2)
void hgemm(const __half* __restrict__ A, int lda,
           const __half* __restrict__ B, int ldb,
           OutT* __restrict__ C, int ldc,
           int K, float alpha)
{
    extern __shared__ char smem[];
    const uint32_t sbase = (uint32_t)__cvta_generic_to_shared(smem);

    const int tid  = threadIdx.x;
    const int lane = tid & 31;
    const int wid  = tid >> 5;           // 0..3
    const int warp_m = (wid & 1) * 64;
    const int warp_n = (wid >> 1) * 64;
    const int bx = blockIdx.x, by = blockIdx.y;
    const int NT = K / 64;

    const __half* Arow = A + (size_t)(by * 128) * lda;
    const __half* Brow = B + (size_t)(bx * 128) * ldb;

    // stage = 32KB: A tile 16KB (128 rows x 128B = 64 halves) | B tile 16KB
    auto load_tile = [&](int buf, int kt) {
        const int k0 = kt * 64;
        char* st = smem + buf * 32768;
        #pragma unroll
        for (int l = 0; l < 8; l++) {
            int c = tid + l * 128;
            int row = c >> 3, ch = c & 7;
            uint32_t off = (uint32_t)(row * 128 + ((ch * 16) ^ ((row & 7) << 4)));
            cpa16(st + off, Arow + (size_t)row * lda + k0 + ch * 8);
        }
        #pragma unroll
        for (int l = 0; l < 8; l++) {
            int c = tid + l * 128;
            int row = c >> 3, ch = c & 7;
            uint32_t off = (uint32_t)(row * 128 + ((ch * 16) ^ ((row & 7) << 4)));
            cpa16(st + 16384 + off, Brow + (size_t)row * ldb + k0 + ch * 8);
        }
        cpa_commit();
    };

    // ldmatrix per-lane addressing (swizzle mask commutes: row bases mult. of 8)
    const uint32_t xmask = (uint32_t)((lane & 7) << 4);
    // A quadrants: {m0,k0},{m8,k0},{m0,k8},{m8,k8}  (k8 = 16 bytes)
    const int a_row = warp_m + (lane & 7) + ((lane >> 3) & 1) * 8;
    const uint32_t a_kh = (uint32_t)((lane >> 4) * 16);
    // B quadrants: {n0,k0},{n0,k8},{n8,k0},{n8,k8}
    const int b_row = warp_n + (lane & 7) + ((lane >> 4) & 1) * 8;
    const uint32_t b_kh = (uint32_t)(((lane >> 3) & 1) * 16);

    const uint32_t a_base = sbase + (uint32_t)(a_row * 128);
    const uint32_t b_base = sbase + 16384u + (uint32_t)(b_row * 128);

    // a[mf]: m16 frag (4 regs) for 64 M-rows; b[pr]: n16 pair (4 regs) for 64 N
    auto lfrag = [&](uint32_t soff, int ks, uint32_t a[4][4], uint32_t b[4][4]) {
        const uint32_t ka = ((uint32_t)(ks * 32) + a_kh) ^ xmask;   // k16 = 32B
        const uint32_t kb = ((uint32_t)(ks * 32) + b_kh) ^ xmask;
        #pragma unroll
        for (int mf = 0; mf < 4; mf++)
            ldsm_x4(a_base + soff + (uint32_t)(mf * 2048) + ka, a[mf]);
        #pragma unroll
        for (int pr = 0; pr < 4; pr++)
            ldsm_x4(b_base + soff + (uint32_t)(pr * 2048) + kb, b[pr]);
    };

    float acc[4][8][4];
    #pragma unroll
    for (int i = 0; i < 4; i++)
        #pragma unroll
        for (int j = 0; j < 8; j++)
            #pragma unroll
            for (int r = 0; r < 4; r++) acc[i][j][r] = 0.f;

    load_tile(0, 0);
    if (NT > 1) load_tile(1, 1);

    for (int kt = 0; kt < NT; kt++) {
        if (kt + 1 < NT) cpa_wait<1>(); else cpa_wait<0>();
        __syncthreads();                       // tile kt ready; all warps past kt-1
        if (kt + 2 < NT) load_tile((kt + 2) % 3, kt + 2);

        const uint32_t soff = (uint32_t)((kt % 3) * 32768);

        uint32_t a[2][4][4];
        uint32_t b[2][4][4];
        lfrag(soff, 0, a[0], b[0]);

        #pragma unroll
        for (int ks = 0; ks < 4; ks++) {       // 4 x k16 per 64-tile
            if (ks < 3) lfrag(soff, ks + 1, a[(ks + 1) & 1], b[(ks + 1) & 1]);
            const uint32_t (*ac)[4] = a[ks & 1];
            const uint32_t (*bc)[4] = b[ks & 1];
            #pragma unroll
            for (int mf = 0; mf < 4; mf++)
                #pragma unroll
                for (int nf = 0; nf < 8; nf++)
                    mma_f16(acc[mf][nf], ac[mf], &bc[nf >> 1][(nf & 1) * 2]);
        }
    }

    // ---- epilogue ----
    const int crow = by * 128 + warp_m + (lane >> 2);
    const int ccol = bx * 128 + warp_n + ((lane & 3) << 1);
    #pragma unroll
    for (int mf = 0; mf < 4; mf++) {
        #pragma unroll
        for (int nf = 0; nf < 8; nf++) {
            st2(C + (size_t)(crow + mf * 16)     * ldc + ccol + nf * 8,
                acc[mf][nf][0] * alpha, acc[mf][nf][1] * alpha);
            st2(C + (size_t)(crow + mf * 16 + 8) * ldc + ccol + nf * 8,
                acc[mf][nf][2] * alpha, acc[mf][nf][3] * alpha);
        }
    }
}

// ---------------------------------------------------------------------------
// Row softmax: S (fp32) -> P (fp16). One block per row, 256 threads.
// ---------------------------------------------------------------------------
__global__ __launch_bounds__(256)
void softmax_kernel(const float* __restrict__ S, __half* __restrict__ P)
{
    constexpr int T = 256;
    constexpr int NV = SEQ / 4 / T;
    __shared__ float red[8];
    __shared__ float bcast;

    const int tid = threadIdx.x;
    const float4* p = (const float4*)(S + (size_t)blockIdx.x * SEQ);
    __half2* q = (__half2*)(P + (size_t)blockIdx.x * SEQ);

    float4 v[NV];
    float mx = -INFINITY;
    #pragma unroll
    for (int i = 0; i < NV; i++) {
        v[i] = p[tid + i * T];
        mx = fmaxf(mx, fmaxf(fmaxf(v[i].x, v[i].y), fmaxf(v[i].z, v[i].w)));
    }
    #pragma unroll
    for (int o = 16; o; o >>= 1) mx = fmaxf(mx, __shfl_xor_sync(0xffffffffu, mx, o));
    if ((tid & 31) == 0) red[tid >> 5] = mx;
    __syncthreads();
    if (tid == 0) {
        float m = red[0];
        #pragma unroll
        for (int i = 1; i < 8; i++) m = fmaxf(m, red[i]);
        bcast = m;
    }
    __syncthreads();
    mx = bcast;

    float sum = 0.f;
    #pragma unroll
    for (int i = 0; i < NV; i++) {
        v[i].x = __expf(v[i].x - mx);
        v[i].y = __expf(v[i].y - mx);
        v[i].z = __expf(v[i].z - mx);
        v[i].w = __expf(v[i].w - mx);
        sum += (v[i].x + v[i].y) + (v[i].z + v[i].w);
    }
    #pragma unroll
    for (int o = 16; o; o >>= 1) sum += __shfl_xor_sync(0xffffffffu, sum, o);
    __syncthreads();
    if ((tid & 31) == 0) red[tid >> 5] = sum;
    __syncthreads();
    if (tid == 0) {
        float s = 0.f;
        #pragma unroll
        for (int i = 0; i < 8; i++) s += red[i];
        bcast = 1.f / s;
    }
    __syncthreads();
    const float inv = bcast;

    #pragma unroll
    for (int i = 0; i < NV; i++) {
        int idx = tid + i * T;
        q[2 * idx + 0] = __floats2half2_rn(v[i].x * inv, v[i].y * inv);
        q[2 * idx + 1] = __floats2half2_rn(v[i].z * inv, v[i].w * inv);
    }
}

// ---------------------------------------------------------------------------
extern "C" void kernel_launch(void* const* d_in, const int* in_sizes, int n_in,
                              void* d_out, int out_size)
{
    const float* E  = (const float*)d_in[0];
    const float* Wq = (const float*)d_in[1];
    const float* Wk = (const float*)d_in[2];
    const float* Wv = (const float*)d_in[3];
    float* out = (float*)d_out;

    __half *Eh, *Wh, *QKVh, *Vth, *P;
    float* S;
    cudaGetSymbolAddress((void**)&Eh,   g_Eh);
    cudaGetSymbolAddress((void**)&Wh,   g_Wh);
    cudaGetSymbolAddress((void**)&QKVh, g_QKVh);
    cudaGetSymbolAddress((void**)&Vth,  g_Vth);
    cudaGetSymbolAddress((void**)&S,    g_S);
    cudaGetSymbolAddress((void**)&P,    g_P);

    constexpr int SMEM_BYTES = 3 * 32768;   // 98304
    cudaFuncSetAttribute(hgemm<float>,
                         cudaFuncAttributeMaxDynamicSharedMemorySize, SMEM_BYTES);
    cudaFuncSetAttribute(hgemm<__half>,
                         cudaFuncAttributeMaxDynamicSharedMemorySize, SMEM_BYTES);

    // prepass: E -> fp16; Wq|Wk|Wv -> transposed fp16 band
    f2h_copy<<<SEQ * DMODEL / 4 / 256, 256>>>((const float4*)E, (__half2*)Eh,
                                              SEQ * DMODEL / 4);
    transpose_w3<<<dim3(32, 32, 3), 256>>>(Wq, Wk, Wv, Wh);

    dim3 blk(128);

    // QKV: [4096,3072] = E @ Wh^T, fp16 out
    hgemm<__half><<<dim3(DQKV / 128, SEQ / 128), blk, SMEM_BYTES>>>(
        Eh, DMODEL, Wh, DMODEL, QKVh, DQKV, DMODEL, 1.0f);

    const __half* Q  = QKVh;
    const __half* Kp = QKVh + DMODEL;
    const __half* V  = QKVh + 2 * DMODEL;

    // V^T: [1024,4096] fp16
    transpose_h<<<dim3(DMODEL / 32, SEQ / 32), 256>>>(V, DQKV, Vth, SEQ);

    // S = (Q @ K^T) / 32, fp32 out
    hgemm<float><<<dim3(SEQ / 128, SEQ / 128), blk, SMEM_BYTES>>>(
        Q, DQKV, Kp, DQKV, S, SEQ, DMODEL, 0.03125f);

    // softmax: S fp32 -> P fp16
    softmax_kernel<<<SEQ, 256>>>(S, P);

    // out = P @ Vt^T, fp32 out
    hgemm<float><<<dim3(DMODEL / 128, SEQ / 128), blk, SMEM_BYTES>>>(
        P, SEQ, Vth, SEQ, out, DMODEL, SEQ, 1.0f);
}